// round 1
// baseline (speedup 1.0000x reference)
#include <cuda_runtime.h>
#include <math.h>
#include <stdint.h>

// ---------------- problem constants ----------------
#define L_    12
#define B_    4
#define H_    12
#define N_    577
#define C_    768
#define D_    64
#define S_    57          // max(1, int(576*0.1))
#define KEEP_ 58          // 577 - int(577*0.9)
#define NNZ_  64
#define ROWS_ (L_*B_*N_)          // 27696 sparse rollout rows
#define BNTOK (B_*N_)             // 2308
#define OUT1_ (B_*N_*C_)          // 1772544
#define OUT2_ (B_*H_*S_*N_)       // 1578672

// ---------------- device scratch (no runtime alloc allowed) ----------------
__device__ int   g_idx[(size_t)ROWS_*NNZ_];
__device__ float g_val[(size_t)ROWS_*NNZ_];
__device__ int   g_cnt[ROWS_];
__device__ float g_scores[B_*(N_-1)];
__device__ int   g_sel[B_*S_];
__device__ int   g_selpos[B_*N_];
__device__ int   g_mark[N_];
__device__ float g_k[(size_t)BNTOK*C_];
__device__ float g_v[(size_t)BNTOK*C_];
__device__ float g_qin[(size_t)B_*S_*C_];
__device__ float g_q[(size_t)B_*S_*C_];
__device__ float g_attnw_scratch[(size_t)B_*H_*S_*N_];
__device__ float g_attnout[(size_t)B_*S_*C_];
__device__ float g_proj[(size_t)B_*S_*C_];

// ---------------- helpers ----------------
__device__ __forceinline__ unsigned fkey(float f) {
    unsigned u = __float_as_uint(f);
    return (u & 0x80000000u) ? ~u : (u | 0x80000000u);
}

__device__ __forceinline__ int block_sum_i(int v, int* sred, int* sres, int nw) {
    int lane = threadIdx.x & 31, w = threadIdx.x >> 5;
#pragma unroll
    for (int o = 16; o > 0; o >>= 1) v += __shfl_down_sync(0xffffffffu, v, o);
    if (lane == 0) sred[w] = v;
    __syncthreads();
    if (threadIdx.x == 0) { int t = 0; for (int k = 0; k < nw; k++) t += sred[k]; *sres = t; }
    __syncthreads();
    return *sres;
}

__device__ __forceinline__ float block_sum_f(float v, float* sred, float* sres, int nw) {
    int lane = threadIdx.x & 31, w = threadIdx.x >> 5;
#pragma unroll
    for (int o = 16; o > 0; o >>= 1) v += __shfl_down_sync(0xffffffffu, v, o);
    if (lane == 0) sred[w] = v;
    __syncthreads();
    if (threadIdx.x == 0) { float t = 0.f; for (int k = 0; k < nw; k++) t += sred[k]; *sres = t; }
    __syncthreads();
    return *sres;
}

__device__ __forceinline__ float block_max_f(float v, float* sred, float* sres, int nw) {
    int lane = threadIdx.x & 31, w = threadIdx.x >> 5;
#pragma unroll
    for (int o = 16; o > 0; o >>= 1) v = fmaxf(v, __shfl_down_sync(0xffffffffu, v, o));
    if (lane == 0) sred[w] = v;
    __syncthreads();
    if (threadIdx.x == 0) { float t = sred[0]; for (int k = 1; k < nw; k++) t = fmaxf(t, sred[k]); *sres = t; }
    __syncthreads();
    return *sres;
}

// ============================================================================
// K1: one block per (layer, batch, row): head-mean, exact top-58 select
//     (bit-exact JAX tie-break), build normalized sparse rollout row.
//     HBM-bound: reads the full 767MB attention_history exactly once.
// ============================================================================
__global__ void __launch_bounds__(128) k_rollout_rows(const float* __restrict__ ah) {
    const int tid = threadIdx.x;
    const int bid = blockIdx.x;           // = (l*B + b)*N + i
    const int i   = bid % N_;
    const int lb  = bid / N_;

    __shared__ float fused[N_];
    __shared__ int   sredi[4];
    __shared__ int   sresi;
    __shared__ float sredf[4];
    __shared__ float sresf;
    __shared__ unsigned char tiesel[N_];
    __shared__ int   s_cnt;
    __shared__ int   s_iin;

    float acc[5];
#pragma unroll
    for (int e = 0; e < 5; e++) acc[e] = 0.f;

    const float* base = ah + (size_t)lb * H_ * N_ * N_ + (size_t)i * N_;
    for (int h = 0; h < H_; h++) {
        const float* p = base + (size_t)h * N_ * N_;
#pragma unroll
        for (int e = 0; e < 5; e++) {
            int j = tid + e * 128;
            if (j < N_) acc[e] += __ldg(&p[j]);
        }
    }
    unsigned key[5];
#pragma unroll
    for (int e = 0; e < 5; e++) {
        int j = tid + e * 128;
        if (j < N_) { float v = acc[e] * (1.f / 12.f); fused[j] = v; key[e] = fkey(v); }
        else key[e] = 0u;
    }
    __syncthreads();

    // exact radix select of the 58th largest key
    unsigned prefix = 0u;
    for (int bit = 31; bit >= 0; bit--) {
        unsigned cand = prefix | (1u << bit);
        int c = 0;
#pragma unroll
        for (int e = 0; e < 5; e++) {
            int j = tid + e * 128;
            if (j < N_ && key[e] >= cand) c++;
        }
        if (block_sum_i(c, sredi, &sresi, 4) >= KEEP_) prefix = cand;
    }
    const unsigned T = prefix;

    int cgt = 0, ceq = 0;
#pragma unroll
    for (int e = 0; e < 5; e++) {
        int j = tid + e * 128;
        if (j < N_) { if (key[e] > T) cgt++; else if (key[e] == T) ceq++; }
    }
    cgt = block_sum_i(cgt, sredi, &sresi, 4);
    ceq = block_sum_i(ceq, sredi, &sresi, 4);
    const int rare = (cgt + ceq) != KEEP_;     // ties beyond quota: resolve by lowest index
    if (rare) {
        if (tid == 0) {
            int rem = KEEP_ - cgt;
            for (int j = 0; j < N_; j++) {
                unsigned char s = 0;
                if (fkey(fused[j]) == T && rem > 0) { s = 1; rem--; }
                tiesel[j] = s;
            }
        }
        __syncthreads();
    }

    if (tid == 0) { s_cnt = 0; s_iin = 0; }
    __syncthreads();

    float dsum = 0.f;
    bool ins[5];
#pragma unroll
    for (int e = 0; e < 5; e++) {
        int j = tid + e * 128;
        ins[e] = false;
        if (j < N_) {
            bool sel = (key[e] > T) || (key[e] == T && (!rare || tiesel[j]));
            bool in  = sel || (j == 0);      // CLS column always kept
            ins[e] = in;
            if (in) {
                dsum += fused[j];
                if (j == i) s_iin = 1;       // single writer
            }
        }
    }
    float denom = block_sum_f(dsum, sredf, &sresf, 4) + 1.f;  // + identity diag
    float invd  = 1.f / denom;

#pragma unroll
    for (int e = 0; e < 5; e++) {
        if (ins[e]) {
            int j = tid + e * 128;
            float v = fused[j] + ((j == i) ? 1.f : 0.f);
            int slot = atomicAdd(&s_cnt, 1);
            g_idx[(size_t)bid * NNZ_ + slot] = j;
            g_val[(size_t)bid * NNZ_ + slot] = v * invd;
        }
    }
    __syncthreads();
    if (tid == 0) {
        int c = s_cnt;
        if (!s_iin) {                         // diag entry from identity only
            g_idx[(size_t)bid * NNZ_ + c] = i;
            g_val[(size_t)bid * NNZ_ + c] = invd;
            c++;
        }
        g_cnt[bid] = c;
    }
}

// ============================================================================
// K2: chain u^T <- u^T * a_l, l = L-1..0, u init = e0. Per-batch block.
//     Only row 0 of the rollout product is ever needed.
// ============================================================================
__global__ void __launch_bounds__(256) k_chain() {
    const int b = blockIdx.x, tid = threadIdx.x;
    __shared__ float u[N_], un[N_];
    for (int j = tid; j < N_; j += 256) { u[j] = (j == 0) ? 1.f : 0.f; g_selpos[b * N_ + j] = -1; }
    if (b == 0) for (int j = tid; j < N_; j += 256) g_mark[j] = 0;
    __syncthreads();
    for (int l = L_ - 1; l >= 0; l--) {
        for (int j = tid; j < N_; j += 256) un[j] = 0.f;
        __syncthreads();
        const int rbase = (l * B_ + b) * N_;
        for (int r = tid; r < N_; r += 256) {
            float ui = u[r];
            if (ui != 0.f) {
                int row = rbase + r;
                int c = g_cnt[row];
                const int*   ip = &g_idx[(size_t)row * NNZ_];
                const float* vp = &g_val[(size_t)row * NNZ_];
                for (int t = 0; t < c; t++) atomicAdd(&un[ip[t]], ui * vp[t]);
            }
        }
        __syncthreads();
        for (int j = tid; j < N_; j += 256) u[j] = un[j];
        __syncthreads();
    }
    for (int j = tid; j < N_; j += 256)
        if (j >= 1) g_scores[b * (N_ - 1) + (j - 1)] = u[j];
}

// ============================================================================
// K3: top-57 of scores per batch, exact JAX order (value desc, index asc).
// ============================================================================
__global__ void __launch_bounds__(256) k_topk() {
    const int b = blockIdx.x, tid = threadIdx.x;
    __shared__ float sv[N_ - 1];
    __shared__ float rv[8];
    __shared__ int   ri[8];
    for (int j = tid; j < N_ - 1; j += 256) sv[j] = g_scores[b * (N_ - 1) + j];
    __syncthreads();
    for (int it = 0; it < S_; it++) {
        float bv = -1.f; int bi2 = 0x7fffffff;
        for (int j = tid; j < N_ - 1; j += 256) {
            float v = sv[j];
            if (v > bv || (v == bv && j < bi2)) { bv = v; bi2 = j; }
        }
        int lane = tid & 31, w = tid >> 5;
#pragma unroll
        for (int o = 16; o > 0; o >>= 1) {
            float ov = __shfl_down_sync(0xffffffffu, bv, o);
            int   oi = __shfl_down_sync(0xffffffffu, bi2, o);
            if (ov > bv || (ov == bv && oi < bi2)) { bv = ov; bi2 = oi; }
        }
        if (lane == 0) { rv[w] = bv; ri[w] = bi2; }
        __syncthreads();
        if (tid == 0) {
            float fv = rv[0]; int fi = ri[0];
            for (int k = 1; k < 8; k++)
                if (rv[k] > fv || (rv[k] == fv && ri[k] < fi)) { fv = rv[k]; fi = ri[k]; }
            int tok = fi + 1;
            g_sel[b * S_ + it] = tok;
            g_selpos[b * N_ + tok] = it;
            g_mark[tok] = 1;
            sv[fi] = -1.f;
        }
        __syncthreads();
    }
}

// ============================================================================
// K4: SGEMM  C[m][n] = bias[n] + sum_k A[m*K+k]*W[n*K+k]  (N = C_ = 768)
//     TM=8 -> 128x64 tiles (big GEMMs), TM=2 -> 32x64 tiles (small GEMMs)
// ============================================================================
template<int TM>
__global__ void __launch_bounds__(256) k_sgemm_nt(const float* __restrict__ A,
                                                  const float* __restrict__ W,
                                                  const float* __restrict__ bias,
                                                  float* __restrict__ Cm,
                                                  int M, int K) {
    constexpr int BM = TM * 16;
    __shared__ float As[16][BM];
    __shared__ float Bs[16][64];
    const int t  = threadIdx.x, tx = t % 16, ty = t / 16;
    const int m0 = blockIdx.y * BM, n0 = blockIdx.x * 64;
    float acc[TM][4];
#pragma unroll
    for (int a = 0; a < TM; a++)
#pragma unroll
        for (int bb = 0; bb < 4; bb++) acc[a][bb] = 0.f;

    for (int k0 = 0; k0 < K; k0 += 16) {
        for (int li = t; li < BM * 4; li += 256) {
            int lm = li >> 2, kq = li & 3;
            int gm = m0 + lm; if (gm >= M) gm = M - 1;
            float4 v = *(const float4*)&A[(size_t)gm * K + k0 + kq * 4];
            As[kq * 4 + 0][lm] = v.x; As[kq * 4 + 1][lm] = v.y;
            As[kq * 4 + 2][lm] = v.z; As[kq * 4 + 3][lm] = v.w;
        }
        {
            int ln = t >> 2, kq = t & 3;   // 64*4 = 256 float4 exactly
            float4 v = *(const float4*)&W[(size_t)(n0 + ln) * K + k0 + kq * 4];
            Bs[kq * 4 + 0][ln] = v.x; Bs[kq * 4 + 1][ln] = v.y;
            Bs[kq * 4 + 2][ln] = v.z; Bs[kq * 4 + 3][ln] = v.w;
        }
        __syncthreads();
#pragma unroll
        for (int kk = 0; kk < 16; kk++) {
            float4 b4 = *(const float4*)&Bs[kk][tx * 4];
            float a_[TM];
#pragma unroll
            for (int a = 0; a < TM; a++) a_[a] = As[kk][ty * TM + a];
#pragma unroll
            for (int a = 0; a < TM; a++) {
                acc[a][0] += a_[a] * b4.x; acc[a][1] += a_[a] * b4.y;
                acc[a][2] += a_[a] * b4.z; acc[a][3] += a_[a] * b4.w;
            }
        }
        __syncthreads();
    }
#pragma unroll
    for (int a = 0; a < TM; a++) {
        int gm = m0 + ty * TM + a;
        if (gm < M) {
#pragma unroll
            for (int bb = 0; bb < 4; bb++) {
                int gn = n0 + tx * 4 + bb;
                Cm[(size_t)gm * C_ + gn] = acc[a][bb] + bias[gn];
            }
        }
    }
}

// gather selected query tokens: g_qin[b*S+s] = x[b, sel[b][s]]
__global__ void __launch_bounds__(192) k_gather_q(const float* __restrict__ x) {
    int bs = blockIdx.x;
    int b = bs / S_;
    int tok = g_sel[bs];
    const float4* src = (const float4*)&x[(size_t)(b * N_ + tok) * C_];
    float4* dst = (float4*)&g_qin[(size_t)bs * C_];
    dst[threadIdx.x] = src[threadIdx.x];
}

// ============================================================================
// K5a: raw attention logits -> attw buffer. Block = (s-chunk of 8, b*H+h).
// ============================================================================
__global__ void __launch_bounds__(256) k_logits(float* __restrict__ attw) {
    const int bh = blockIdx.y, b = bh / H_, h = bh % H_;
    const int s0 = blockIdx.x * 8;
    const int t  = threadIdx.x;
    __shared__ float qs[8][64];
    __shared__ float ks[32][65];
#pragma unroll
    for (int e = 0; e < 2; e++) {
        int li = t + e * 256; int qq = li >> 6, d = li & 63; int s = s0 + qq;
        qs[qq][d] = (s < S_) ? g_q[(size_t)(b * S_ + s) * C_ + h * 64 + d] : 0.f;
    }
    const int myq = t >> 5, nn = t & 31;
    for (int n0 = 0; n0 < N_; n0 += 32) {
#pragma unroll
        for (int e = 0; e < 8; e++) {
            int li = t + e * 256; int r = li >> 6, d = li & 63; int n = n0 + r;
            ks[r][d] = (n < N_) ? g_k[(size_t)(b * N_ + n) * C_ + h * 64 + d] : 0.f;
        }
        __syncthreads();
        float a = 0.f;
#pragma unroll
        for (int d = 0; d < 64; d++) a += qs[myq][d] * ks[nn][d];
        int n = n0 + nn, s = s0 + myq;
        if (n < N_ && s < S_) attw[((size_t)bh * S_ + s) * N_ + n] = a * 0.125f;
        __syncthreads();
    }
}

// K5b: row softmax in place (rows of 577).
__global__ void __launch_bounds__(128) k_softmax(float* __restrict__ attw) {
    float* row = attw + (size_t)blockIdx.x * N_;
    const int tid = threadIdx.x;
    __shared__ float sredf[4];
    __shared__ float sresf;
    float v[5];
#pragma unroll
    for (int e = 0; e < 5; e++) { int j = tid + e * 128; v[e] = (j < N_) ? row[j] : -INFINITY; }
    float m = v[0];
#pragma unroll
    for (int e = 1; e < 5; e++) m = fmaxf(m, v[e]);
    m = block_max_f(m, sredf, &sresf, 4);
    float s = 0.f;
#pragma unroll
    for (int e = 0; e < 5; e++) {
        int j = tid + e * 128;
        if (j < N_) { v[e] = expf(v[e] - m); s += v[e]; }
    }
    s = block_sum_f(s, sredf, &sresf, 4);
    float inv = 1.f / s;
#pragma unroll
    for (int e = 0; e < 5; e++) {
        int j = tid + e * 128;
        if (j < N_) row[j] = v[e] * inv;
    }
}

// K5c: out[b,s,h,d] = sum_n attw[b,h,s,n] * v[b,n,h,d]; block per (b,h).
__global__ void __launch_bounds__(256) k_av(const float* __restrict__ attw) {
    const int bh = blockIdx.x, b = bh / H_, h = bh % H_;
    const int t = threadIdx.x, d = t & 63, sb = t >> 6;
    __shared__ float vs[32][64];
    __shared__ float ws[S_][32];
    float acc[15];
#pragma unroll
    for (int k = 0; k < 15; k++) acc[k] = 0.f;
    for (int n0 = 0; n0 < N_; n0 += 32) {
#pragma unroll
        for (int e = 0; e < 8; e++) {
            int li = t + e * 256; int r = li >> 6, dd = li & 63; int n = n0 + r;
            vs[r][dd] = (n < N_) ? g_v[(size_t)(b * N_ + n) * C_ + h * 64 + dd] : 0.f;
        }
        for (int li = t; li < S_ * 32; li += 256) {
            int s = li >> 5, nn = li & 31; int n = n0 + nn;
            ws[s][nn] = (n < N_) ? attw[((size_t)bh * S_ + s) * N_ + n] : 0.f;
        }
        __syncthreads();
        float vv[32];
#pragma unroll
        for (int nn = 0; nn < 32; nn++) vv[nn] = vs[nn][d];
#pragma unroll
        for (int k = 0; k < 15; k++) {
            int s = sb + 4 * k;
            if (s < S_) {
                float a = acc[k];
#pragma unroll
                for (int nn = 0; nn < 32; nn++) a += ws[s][nn] * vv[nn];
                acc[k] = a;
            }
        }
        __syncthreads();
    }
#pragma unroll
    for (int k = 0; k < 15; k++) {
        int s = sb + 4 * k;
        if (s < S_) g_attnout[(size_t)(b * S_ + s) * C_ + h * 64 + d] = acc[k];
    }
}

// ============================================================================
// K7: assemble final output per (b, token): CLS copy, selected -> proj,
//     selected-in-other-batch -> 0, else copy x.
// ============================================================================
__global__ void __launch_bounds__(192) k_assemble(const float* __restrict__ x,
                                                  float* __restrict__ out) {
    const int bj = blockIdx.x;
    const int b = bj / N_, j = bj % N_;
    const int t = threadIdx.x;
    float4* dst = (float4*)&out[(size_t)bj * C_];
    const float4* xs = (const float4*)&x[(size_t)bj * C_];
    if (j == 0) { dst[t] = xs[t]; return; }
    int p = g_selpos[b * N_ + j];
    if (p >= 0) {
        const float4* ps = (const float4*)&g_proj[(size_t)(b * S_ + p) * C_];
        dst[t] = ps[t];
    } else if (g_mark[j]) {
        dst[t] = make_float4(0.f, 0.f, 0.f, 0.f);
    } else {
        dst[t] = xs[t];
    }
}

// ============================================================================
extern "C" void kernel_launch(void* const* d_in, const int* in_sizes, int n_in,
                              void* d_out, int out_size) {
    const float* x  = (const float*)d_in[0];
    const float* ah = (const float*)d_in[1];
    const float* Wq = (const float*)d_in[2];
    const float* bq = (const float*)d_in[3];
    const float* Wk = (const float*)d_in[4];
    const float* bk = (const float*)d_in[5];
    const float* Wv = (const float*)d_in[6];
    const float* bv = (const float*)d_in[7];
    const float* Wo = (const float*)d_in[8];
    const float* bo = (const float*)d_in[9];
    float* out = (float*)d_out;

    float *pk, *pv, *pqin, *pq, *pao, *ppr, *pattn;
    cudaGetSymbolAddress((void**)&pk,    g_k);
    cudaGetSymbolAddress((void**)&pv,    g_v);
    cudaGetSymbolAddress((void**)&pqin,  g_qin);
    cudaGetSymbolAddress((void**)&pq,    g_q);
    cudaGetSymbolAddress((void**)&pao,   g_attnout);
    cudaGetSymbolAddress((void**)&ppr,   g_proj);
    cudaGetSymbolAddress((void**)&pattn, g_attnw_scratch);

    // attn_w goes straight into d_out when the harness expects both outputs
    float* attw = (out_size >= OUT1_ + OUT2_) ? (out + OUT1_) : pattn;

    // rollout (sparse) + selection
    k_rollout_rows<<<ROWS_, 128>>>(ah);
    k_chain<<<B_, 256>>>();
    k_topk<<<B_, 256>>>();

    // projections
    k_sgemm_nt<8><<<dim3(C_ / 64, (BNTOK + 127) / 128), 256>>>(x, Wk, bk, pk, BNTOK, C_);
    k_sgemm_nt<8><<<dim3(C_ / 64, (BNTOK + 127) / 128), 256>>>(x, Wv, bv, pv, BNTOK, C_);
    k_gather_q<<<B_ * S_, 192>>>(x);
    k_sgemm_nt<2><<<dim3(C_ / 64, (B_ * S_ + 31) / 32), 256>>>(pqin, Wq, bq, pq, B_ * S_, C_);

    // attention
    k_logits<<<dim3(8, B_ * H_), 256>>>(attw);
    k_softmax<<<B_ * H_ * S_, 128>>>(attw);
    k_av<<<B_ * H_, 256>>>(attw);

    // output projection + scatter
    k_sgemm_nt<2><<<dim3(C_ / 64, (B_ * S_ + 31) / 32), 256>>>(pao, Wo, bo, ppr, B_ * S_, C_);
    k_assemble<<<BNTOK, 192>>>(x, out);
}

// round 2
// speedup vs baseline: 2.2901x; 2.2901x over previous
#include <cuda_runtime.h>
#include <math.h>
#include <stdint.h>

// ---------------- problem constants ----------------
#define L_    12
#define B_    4
#define H_    12
#define N_    577
#define C_    768
#define D_    64
#define S_    57
#define KEEP_ 58
#define RP_   580                  // padded AT row length (multiple of 4)
#define ROWS_ (L_*B_*N_)           // 27696
#define BNTOK (B_*N_)              // 2308
#define OUT1_ (B_*N_*C_)
#define OUT2_ (B_*H_*S_*N_)
#define AT_FLOATS ((size_t)L_*B_*N_*RP_)   // 16,063,680

// ---------------- device scratch ----------------
__device__ float g_AT[AT_FLOATS];          // dense transposed rollout mats
__device__ float g_u0[B_*N_];
__device__ float g_u1[B_*N_];
__device__ float g_scores[B_*(N_-1)];
__device__ int   g_sel[B_*S_];
__device__ int   g_selpos[B_*N_];
__device__ int   g_mark[N_];
__device__ float g_k[(size_t)BNTOK*C_];
__device__ float g_v[(size_t)BNTOK*C_];
__device__ float g_qin[(size_t)B_*S_*C_];
__device__ float g_q[(size_t)B_*S_*C_];
__device__ float g_attnw_scratch[(size_t)B_*H_*S_*N_];
__device__ float g_attnout[(size_t)B_*S_*C_];
__device__ float g_proj[(size_t)B_*S_*C_];

// ---------------- helpers ----------------
__device__ __forceinline__ unsigned fkey(float f) {
    unsigned u = __float_as_uint(f);
    return (u & 0x80000000u) ? ~u : (u | 0x80000000u);
}
__device__ __forceinline__ int wsum_i(int v) {
#pragma unroll
    for (int o = 16; o > 0; o >>= 1) v += __shfl_xor_sync(0xffffffffu, v, o);
    return v;
}
__device__ __forceinline__ float wsum_f(float v) {
#pragma unroll
    for (int o = 16; o > 0; o >>= 1) v += __shfl_xor_sync(0xffffffffu, v, o);
    return v;
}
__device__ __forceinline__ float block_sum_f(float v, float* sred, float* sres, int nw) {
    int lane = threadIdx.x & 31, w = threadIdx.x >> 5;
#pragma unroll
    for (int o = 16; o > 0; o >>= 1) v += __shfl_down_sync(0xffffffffu, v, o);
    if (lane == 0) sred[w] = v;
    __syncthreads();
    if (threadIdx.x == 0) { float t = 0.f; for (int k = 0; k < nw; k++) t += sred[k]; *sres = t; }
    __syncthreads();
    return *sres;
}
__device__ __forceinline__ float block_max_f(float v, float* sred, float* sres, int nw) {
    int lane = threadIdx.x & 31, w = threadIdx.x >> 5;
#pragma unroll
    for (int o = 16; o > 0; o >>= 1) v = fmaxf(v, __shfl_down_sync(0xffffffffu, v, o));
    if (lane == 0) sred[w] = v;
    __syncthreads();
    if (threadIdx.x == 0) { float t = sred[0]; for (int k = 1; k < nw; k++) t = fmaxf(t, sred[k]); *sres = t; }
    __syncthreads();
    return *sres;
}

// ============================================================================
// K0: zero AT (float4 grid-stride)
// ============================================================================
__global__ void __launch_bounds__(256) k_zero_at() {
    float4* p = (float4*)g_AT;
    size_t n4 = AT_FLOATS / 4;
    for (size_t i = blockIdx.x * 256ull + threadIdx.x; i < n4; i += (size_t)gridDim.x * 256ull)
        p[i] = make_float4(0.f, 0.f, 0.f, 0.f);
}

// K0b: init u0 = e0 per batch, selpos = -1, mark = 0
__global__ void __launch_bounds__(256) k_init() {
    int i = blockIdx.x * 256 + threadIdx.x;
    if (i < B_ * N_) {
        g_u0[i] = ((i % N_) == 0) ? 1.f : 0.f;
        g_selpos[i] = -1;
    }
    if (i < N_) g_mark[i] = 0;
}

// ============================================================================
// K1: warp per (layer,batch,row). Head-mean, warp radix top-58 (exact JAX
//     tie-break), write normalized dense transposed rollout row into AT.
//     No block barriers; warp shfl reductions only.
// ============================================================================
__global__ void __launch_bounds__(256) k_rollout(const float* __restrict__ ah) {
    const int w    = threadIdx.x >> 5;
    const int lane = threadIdx.x & 31;
    const int row  = blockIdx.x * 8 + w;          // 0..27695 (grid = 3462)
    const int i    = row % N_;
    const int lb   = row / N_;

    __shared__ float    fused_s[8][N_];
    __shared__ unsigned tiemask[8][19];

    float val[19];
#pragma unroll
    for (int e = 0; e < 19; e++) val[e] = 0.f;

    const float* base = ah + (size_t)lb * H_ * N_ * N_ + (size_t)i * N_;
#pragma unroll 1
    for (int h = 0; h < H_; h++) {
        const float* p = base + (size_t)h * N_ * N_;
#pragma unroll
        for (int e = 0; e < 19; e++) {
            int j = lane + 32 * e;
            if (j < N_) val[e] += __ldg(&p[j]);
        }
    }
    unsigned key[19];
#pragma unroll
    for (int e = 0; e < 19; e++) {
        int j = lane + 32 * e;
        if (j < N_) { val[e] *= (1.f / 12.f); key[e] = fkey(val[e]); }
        else key[e] = 0u;
    }

    // warp radix select: T = 58th largest key
    unsigned prefix = 0u;
#pragma unroll 1
    for (int bit = 31; bit >= 0; bit--) {
        unsigned cand = prefix | (1u << bit);
        int c = 0;
#pragma unroll
        for (int e = 0; e < 19; e++) c += (key[e] >= cand);
        if (wsum_i(c) >= KEEP_) prefix = cand;
    }
    const unsigned T = prefix;

    int cgt = 0, ceq = 0;
#pragma unroll
    for (int e = 0; e < 19; e++) { cgt += (key[e] > T); ceq += (key[e] == T); }
    cgt = wsum_i(cgt);
    ceq = wsum_i(ceq);
    const bool rare = (cgt + ceq) != KEEP_;

    if (rare) {       // tie spill: resolve by lowest index, serial on lane 0
#pragma unroll
        for (int e = 0; e < 19; e++) {
            int j = lane + 32 * e;
            if (j < N_) fused_s[w][j] = val[e];
        }
        __syncwarp();
        if (lane == 0) {
#pragma unroll
            for (int q = 0; q < 19; q++) tiemask[w][q] = 0u;
            int rem = KEEP_ - cgt;
            for (int j = 0; j < N_ && rem > 0; j++) {
                if (fkey(fused_s[w][j]) == T) { tiemask[w][j >> 5] |= 1u << (j & 31); rem--; }
            }
        }
        __syncwarp();
    }

    bool inc[19];
    float dsum = 0.f;
    bool iin_local = false;
#pragma unroll
    for (int e = 0; e < 19; e++) {
        int j = lane + 32 * e;
        inc[e] = false;
        if (j < N_) {
            bool tieb = rare ? ((tiemask[w][j >> 5] >> (j & 31)) & 1u) : true;
            bool sel = (key[e] > T) || (key[e] == T && tieb);
            bool in  = sel || (j == 0);
            inc[e] = in;
            if (in) { dsum += val[e]; if (j == i) iin_local = true; }
        }
    }
    float denom = wsum_f(dsum) + 1.f;
    float invd  = 1.f / denom;
    bool iin = __any_sync(0xffffffffu, iin_local);

    float* atb = g_AT + (size_t)lb * N_ * RP_;
#pragma unroll
    for (int e = 0; e < 19; e++) {
        if (inc[e]) {
            int j = lane + 32 * e;
            atb[(size_t)j * RP_ + i] = (val[e] + ((j == i) ? 1.f : 0.f)) * invd;
        }
    }
    if (!iin && lane == 0) atb[(size_t)i * RP_ + i] = invd;
}

// ============================================================================
// K2: one chain step  un[j] = sum_r u[r] * AT[lb][j][r]  (gather, no atomics)
// ============================================================================
__global__ void __launch_bounds__(256) k_chain_step(const float* __restrict__ uin,
                                                    float* __restrict__ uout,
                                                    int l, int final_step) {
    const int b = blockIdx.y;
    const int lb = l * B_ + b;
    __shared__ float us[RP_];
    for (int idx = threadIdx.x; idx < RP_; idx += 256)
        us[idx] = (idx < N_) ? uin[b * N_ + idx] : 0.f;
    __syncthreads();

    const int w = threadIdx.x >> 5, lane = threadIdx.x & 31;
    const int j = blockIdx.x * 8 + w;
    if (j >= N_) return;
    const float4* rowp = (const float4*)(g_AT + ((size_t)lb * N_ + j) * RP_);
    float s = 0.f;
#pragma unroll
    for (int e = 0; e < 5; e++) {
        int idx = lane + 32 * e;
        if (idx < RP_ / 4) {
            float4 v = rowp[idx];
            s += v.x * us[4 * idx] + v.y * us[4 * idx + 1]
               + v.z * us[4 * idx + 2] + v.w * us[4 * idx + 3];
        }
    }
    s = wsum_f(s);
    if (lane == 0) {
        if (final_step) { if (j >= 1) g_scores[b * (N_ - 1) + (j - 1)] = s; }
        else uout[b * N_ + j] = s;
    }
}

// ============================================================================
// K3: top-57 of scores per batch, exact JAX order (value desc, index asc)
// ============================================================================
__global__ void __launch_bounds__(256) k_topk() {
    const int b = blockIdx.x, tid = threadIdx.x;
    __shared__ float sv[N_ - 1];
    __shared__ float rv[8];
    __shared__ int   ri[8];
    for (int j = tid; j < N_ - 1; j += 256) sv[j] = g_scores[b * (N_ - 1) + j];
    __syncthreads();
    for (int it = 0; it < S_; it++) {
        float bv = -1.f; int bi2 = 0x7fffffff;
        for (int j = tid; j < N_ - 1; j += 256) {
            float v = sv[j];
            if (v > bv || (v == bv && j < bi2)) { bv = v; bi2 = j; }
        }
        int lane = tid & 31, w = tid >> 5;
#pragma unroll
        for (int o = 16; o > 0; o >>= 1) {
            float ov = __shfl_down_sync(0xffffffffu, bv, o);
            int   oi = __shfl_down_sync(0xffffffffu, bi2, o);
            if (ov > bv || (ov == bv && oi < bi2)) { bv = ov; bi2 = oi; }
        }
        if (lane == 0) { rv[w] = bv; ri[w] = bi2; }
        __syncthreads();
        if (tid == 0) {
            float fv = rv[0]; int fi = ri[0];
            for (int k = 1; k < 8; k++)
                if (rv[k] > fv || (rv[k] == fv && ri[k] < fi)) { fv = rv[k]; fi = ri[k]; }
            int tok = fi + 1;
            g_sel[b * S_ + it] = tok;
            g_selpos[b * N_ + tok] = it;
            g_mark[tok] = 1;
            sv[fi] = -1.f;
        }
        __syncthreads();
    }
}

// ============================================================================
// K4: 128x128x8 SGEMM (NT), 8x8/thread quadrant layout. z picks {K,V}.
//     C[m][n] = bias[n] + sum_k A[m][k]*W[n][k]
// ============================================================================
__global__ void __launch_bounds__(256) k_sgemm128(const float* __restrict__ A,
                                                  const float* __restrict__ Wk_,
                                                  const float* __restrict__ Wv_,
                                                  const float* __restrict__ bk_,
                                                  const float* __restrict__ bv_,
                                                  float* __restrict__ Ck_,
                                                  float* __restrict__ Cv_,
                                                  int M) {
    const float* W    = blockIdx.z ? Wv_ : Wk_;
    const float* bias = blockIdx.z ? bv_ : bk_;
    float*       Cm   = blockIdx.z ? Cv_ : Ck_;

    __shared__ float As[8][132];
    __shared__ float Bs[8][132];
    const int t = threadIdx.x;
    const int m0 = blockIdx.y * 128, n0 = blockIdx.x * 128;
    const int lr = t >> 1, lc = (t & 1) * 4;
    const int ty4 = (t >> 4) * 4, tx4 = (t & 15) * 4;

    float acc[2][2][4][4];
#pragma unroll
    for (int p = 0; p < 2; p++)
#pragma unroll
        for (int q = 0; q < 2; q++)
#pragma unroll
            for (int ii = 0; ii < 4; ii++)
#pragma unroll
                for (int jj = 0; jj < 4; jj++) acc[p][q][ii][jj] = 0.f;

    int gm = m0 + lr; if (gm >= M) gm = M - 1;
    const float* arow = A + (size_t)gm * C_;
    const float* wrow = W + (size_t)(n0 + lr) * C_;

    for (int k0 = 0; k0 < C_; k0 += 8) {
        float4 av = *(const float4*)&arow[k0 + lc];
        float4 wv = *(const float4*)&wrow[k0 + lc];
        As[lc + 0][lr] = av.x; As[lc + 1][lr] = av.y; As[lc + 2][lr] = av.z; As[lc + 3][lr] = av.w;
        Bs[lc + 0][lr] = wv.x; Bs[lc + 1][lr] = wv.y; Bs[lc + 2][lr] = wv.z; Bs[lc + 3][lr] = wv.w;
        __syncthreads();
#pragma unroll
        for (int kk = 0; kk < 8; kk++) {
            float4 a0 = *(const float4*)&As[kk][ty4];
            float4 a1 = *(const float4*)&As[kk][64 + ty4];
            float4 b0 = *(const float4*)&Bs[kk][tx4];
            float4 b1 = *(const float4*)&Bs[kk][64 + tx4];
            const float ar[2][4] = {{a0.x, a0.y, a0.z, a0.w}, {a1.x, a1.y, a1.z, a1.w}};
            const float br[2][4] = {{b0.x, b0.y, b0.z, b0.w}, {b1.x, b1.y, b1.z, b1.w}};
#pragma unroll
            for (int p = 0; p < 2; p++)
#pragma unroll
                for (int ii = 0; ii < 4; ii++)
#pragma unroll
                    for (int q = 0; q < 2; q++)
#pragma unroll
                        for (int jj = 0; jj < 4; jj++)
                            acc[p][q][ii][jj] += ar[p][ii] * br[q][jj];
        }
        __syncthreads();
    }
#pragma unroll
    for (int p = 0; p < 2; p++)
#pragma unroll
        for (int ii = 0; ii < 4; ii++) {
            int m = m0 + p * 64 + ty4 + ii;
            if (m < M) {
#pragma unroll
                for (int q = 0; q < 2; q++) {
                    int n = n0 + q * 64 + tx4;
                    float4 bv4 = *(const float4*)&bias[n];
                    float4 o;
                    o.x = acc[p][q][ii][0] + bv4.x;
                    o.y = acc[p][q][ii][1] + bv4.y;
                    o.z = acc[p][q][ii][2] + bv4.z;
                    o.w = acc[p][q][ii][3] + bv4.w;
                    *(float4*)&Cm[(size_t)m * C_ + n] = o;
                }
            }
        }
}

// small-M SGEMM (32x64 tiles) for Q / output projections
template<int TM>
__global__ void __launch_bounds__(256) k_sgemm_nt(const float* __restrict__ A,
                                                  const float* __restrict__ W,
                                                  const float* __restrict__ bias,
                                                  float* __restrict__ Cm,
                                                  int M, int K) {
    constexpr int BM = TM * 16;
    __shared__ float As[16][BM];
    __shared__ float Bs[16][64];
    const int t  = threadIdx.x, tx = t % 16, ty = t / 16;
    const int m0 = blockIdx.y * BM, n0 = blockIdx.x * 64;
    float acc[TM][4];
#pragma unroll
    for (int a = 0; a < TM; a++)
#pragma unroll
        for (int bb = 0; bb < 4; bb++) acc[a][bb] = 0.f;

    for (int k0 = 0; k0 < K; k0 += 16) {
        for (int li = t; li < BM * 4; li += 256) {
            int lm = li >> 2, kq = li & 3;
            int gm = m0 + lm; if (gm >= M) gm = M - 1;
            float4 v = *(const float4*)&A[(size_t)gm * K + k0 + kq * 4];
            As[kq * 4 + 0][lm] = v.x; As[kq * 4 + 1][lm] = v.y;
            As[kq * 4 + 2][lm] = v.z; As[kq * 4 + 3][lm] = v.w;
        }
        {
            int ln = t >> 2, kq = t & 3;
            float4 v = *(const float4*)&W[(size_t)(n0 + ln) * K + k0 + kq * 4];
            Bs[kq * 4 + 0][ln] = v.x; Bs[kq * 4 + 1][ln] = v.y;
            Bs[kq * 4 + 2][ln] = v.z; Bs[kq * 4 + 3][ln] = v.w;
        }
        __syncthreads();
#pragma unroll
        for (int kk = 0; kk < 16; kk++) {
            float4 b4 = *(const float4*)&Bs[kk][tx * 4];
            float a_[TM];
#pragma unroll
            for (int a = 0; a < TM; a++) a_[a] = As[kk][ty * TM + a];
#pragma unroll
            for (int a = 0; a < TM; a++) {
                acc[a][0] += a_[a] * b4.x; acc[a][1] += a_[a] * b4.y;
                acc[a][2] += a_[a] * b4.z; acc[a][3] += a_[a] * b4.w;
            }
        }
        __syncthreads();
    }
#pragma unroll
    for (int a = 0; a < TM; a++) {
        int gm = m0 + ty * TM + a;
        if (gm < M) {
#pragma unroll
            for (int bb = 0; bb < 4; bb++) {
                int gn = n0 + tx * 4 + bb;
                Cm[(size_t)gm * C_ + gn] = acc[a][bb] + bias[gn];
            }
        }
    }
}

__global__ void __launch_bounds__(192) k_gather_q(const float* __restrict__ x) {
    int bs = blockIdx.x;
    int b = bs / S_;
    int tok = g_sel[bs];
    const float4* src = (const float4*)&x[(size_t)(b * N_ + tok) * C_];
    float4* dst = (float4*)&g_qin[(size_t)bs * C_];
    dst[threadIdx.x] = src[threadIdx.x];
}

// ============================================================================
// K5a/b/c: logits, softmax, A@V
// ============================================================================
__global__ void __launch_bounds__(256) k_logits(float* __restrict__ attw) {
    const int bh = blockIdx.y, b = bh / H_, h = bh % H_;
    const int s0 = blockIdx.x * 8;
    const int t  = threadIdx.x;
    __shared__ float qs[8][64];
    __shared__ float ks[32][65];
#pragma unroll
    for (int e = 0; e < 2; e++) {
        int li = t + e * 256; int qq = li >> 6, d = li & 63; int s = s0 + qq;
        qs[qq][d] = (s < S_) ? g_q[(size_t)(b * S_ + s) * C_ + h * 64 + d] : 0.f;
    }
    const int myq = t >> 5, nn = t & 31;
    for (int n0 = 0; n0 < N_; n0 += 32) {
#pragma unroll
        for (int e = 0; e < 8; e++) {
            int li = t + e * 256; int r = li >> 6, d = li & 63; int n = n0 + r;
            ks[r][d] = (n < N_) ? g_k[(size_t)(b * N_ + n) * C_ + h * 64 + d] : 0.f;
        }
        __syncthreads();
        float a = 0.f;
#pragma unroll
        for (int d = 0; d < 64; d++) a += qs[myq][d] * ks[nn][d];
        int n = n0 + nn, s = s0 + myq;
        if (n < N_ && s < S_) attw[((size_t)bh * S_ + s) * N_ + n] = a * 0.125f;
        __syncthreads();
    }
}

__global__ void __launch_bounds__(128) k_softmax(float* __restrict__ attw) {
    float* row = attw + (size_t)blockIdx.x * N_;
    const int tid = threadIdx.x;
    __shared__ float sredf[4];
    __shared__ float sresf;
    float v[5];
#pragma unroll
    for (int e = 0; e < 5; e++) { int j = tid + e * 128; v[e] = (j < N_) ? row[j] : -INFINITY; }
    float m = v[0];
#pragma unroll
    for (int e = 1; e < 5; e++) m = fmaxf(m, v[e]);
    m = block_max_f(m, sredf, &sresf, 4);
    float s = 0.f;
#pragma unroll
    for (int e = 0; e < 5; e++) {
        int j = tid + e * 128;
        if (j < N_) { v[e] = expf(v[e] - m); s += v[e]; }
    }
    s = block_sum_f(s, sredf, &sresf, 4);
    float inv = 1.f / s;
#pragma unroll
    for (int e = 0; e < 5; e++) {
        int j = tid + e * 128;
        if (j < N_) row[j] = v[e] * inv;
    }
}

__global__ void __launch_bounds__(256) k_av(const float* __restrict__ attw) {
    const int bh = blockIdx.x, b = bh / H_, h = bh % H_;
    const int t = threadIdx.x, d = t & 63, sb = t >> 6;
    __shared__ float vs[32][64];
    __shared__ float ws[S_][32];
    float acc[15];
#pragma unroll
    for (int k = 0; k < 15; k++) acc[k] = 0.f;
    for (int n0 = 0; n0 < N_; n0 += 32) {
#pragma unroll
        for (int e = 0; e < 8; e++) {
            int li = t + e * 256; int r = li >> 6, dd = li & 63; int n = n0 + r;
            vs[r][dd] = (n < N_) ? g_v[(size_t)(b * N_ + n) * C_ + h * 64 + dd] : 0.f;
        }
        for (int li = t; li < S_ * 32; li += 256) {
            int s = li >> 5, nn = li & 31; int n = n0 + nn;
            ws[s][nn] = (n < N_) ? attw[((size_t)bh * S_ + s) * N_ + n] : 0.f;
        }
        __syncthreads();
        float vv[32];
#pragma unroll
        for (int nn = 0; nn < 32; nn++) vv[nn] = vs[nn][d];
#pragma unroll
        for (int k = 0; k < 15; k++) {
            int s = sb + 4 * k;
            if (s < S_) {
                float a = acc[k];
#pragma unroll
                for (int nn = 0; nn < 32; nn++) a += ws[s][nn] * vv[nn];
                acc[k] = a;
            }
        }
        __syncthreads();
    }
#pragma unroll
    for (int k = 0; k < 15; k++) {
        int s = sb + 4 * k;
        if (s < S_) g_attnout[(size_t)(b * S_ + s) * C_ + h * 64 + d] = acc[k];
    }
}

__global__ void __launch_bounds__(192) k_assemble(const float* __restrict__ x,
                                                  float* __restrict__ out) {
    const int bj = blockIdx.x;
    const int b = bj / N_, j = bj % N_;
    const int t = threadIdx.x;
    float4* dst = (float4*)&out[(size_t)bj * C_];
    const float4* xs = (const float4*)&x[(size_t)bj * C_];
    if (j == 0) { dst[t] = xs[t]; return; }
    int p = g_selpos[b * N_ + j];
    if (p >= 0) {
        const float4* ps = (const float4*)&g_proj[(size_t)(b * S_ + p) * C_];
        dst[t] = ps[t];
    } else if (g_mark[j]) {
        dst[t] = make_float4(0.f, 0.f, 0.f, 0.f);
    } else {
        dst[t] = xs[t];
    }
}

// ============================================================================
extern "C" void kernel_launch(void* const* d_in, const int* in_sizes, int n_in,
                              void* d_out, int out_size) {
    const float* x  = (const float*)d_in[0];
    const float* ah = (const float*)d_in[1];
    const float* Wq = (const float*)d_in[2];
    const float* bq = (const float*)d_in[3];
    const float* Wk = (const float*)d_in[4];
    const float* bk = (const float*)d_in[5];
    const float* Wv = (const float*)d_in[6];
    const float* bv = (const float*)d_in[7];
    const float* Wo = (const float*)d_in[8];
    const float* bo = (const float*)d_in[9];
    float* out = (float*)d_out;

    float *pk, *pv, *pqin, *pq, *pao, *ppr, *pattn, *pu0, *pu1;
    cudaGetSymbolAddress((void**)&pk,    g_k);
    cudaGetSymbolAddress((void**)&pv,    g_v);
    cudaGetSymbolAddress((void**)&pqin,  g_qin);
    cudaGetSymbolAddress((void**)&pq,    g_q);
    cudaGetSymbolAddress((void**)&pao,   g_attnout);
    cudaGetSymbolAddress((void**)&ppr,   g_proj);
    cudaGetSymbolAddress((void**)&pattn, g_attnw_scratch);
    cudaGetSymbolAddress((void**)&pu0,   g_u0);
    cudaGetSymbolAddress((void**)&pu1,   g_u1);

    float* attw = (out_size >= OUT1_ + OUT2_) ? (out + OUT1_) : pattn;

    // rollout
    k_zero_at<<<2048, 256>>>();
    k_init<<<(B_ * N_ + 255) / 256, 256>>>();
    k_rollout<<<ROWS_ / 8, 256>>>(ah);
    {
        float* uin = pu0; float* uout = pu1;
        for (int l = L_ - 1; l >= 0; l--) {
            int fin = (l == 0);
            k_chain_step<<<dim3(73, B_), 256>>>(uin, uout, l, fin);
            float* tmp = uin; uin = uout; uout = tmp;
        }
    }
    k_topk<<<B_, 256>>>();

    // projections
    k_sgemm128<<<dim3(C_ / 128, (BNTOK + 127) / 128, 2), 256>>>(x, Wk, Wv, bk, bv, pk, pv, BNTOK);
    k_gather_q<<<B_ * S_, 192>>>(x);
    k_sgemm_nt<2><<<dim3(C_ / 64, (B_ * S_ + 31) / 32), 256>>>(pqin, Wq, bq, pq, B_ * S_, C_);

    // attention
    k_logits<<<dim3(8, B_ * H_), 256>>>(attw);
    k_softmax<<<B_ * H_ * S_, 128>>>(attw);
    k_av<<<B_ * H_, 256>>>(attw);

    // output projection + scatter
    k_sgemm_nt<2><<<dim3(C_ / 64, (B_ * S_ + 31) / 32), 256>>>(pao, Wo, bo, ppr, B_ * S_, C_);
    k_assemble<<<BNTOK, 192>>>(x, out);
}